// round 1
// baseline (speedup 1.0000x reference)
#include <cuda_runtime.h>
#include <cstdint>
#include <cstddef>

#define BB 4
#define NQ 16384
#define MP 4096
#define C1V 128
#define C2V 256
#define D0 256
#define D1 128
#define NTOT (BB*NQ)   // 65536

// ---------------- scratch (device globals; no allocation allowed) ----------------
__device__ float4 g_xyz2p[BB*MP];                 // packed xyz2 + norm
__device__ float  g_sc0[D0], g_sh0[D0], g_sc1[D1], g_sh1[D1];
__device__ float  g_wgt[NTOT*3];
__device__ int    g_idx[NTOT*3];
__device__ float  g_P2W[BB*MP*D0];                // points2 @ w0[0:256,:]   (16 MB)
__device__ float  g_G1[(size_t)NTOT*D0];          // gathered first-layer partial (64 MB)
__device__ float  g_H[(size_t)NTOT*D0];           // layer-1 activations (64 MB)

// ---------------- small helpers ----------------
__device__ __forceinline__ uint32_t f2tf(float x){
    uint32_t r;
    asm("cvt.rna.tf32.f32 %0, %1;" : "=r"(r) : "f"(x));
    return r;
}

__device__ __forceinline__ void mma_tf32(float* c, const uint32_t* a, const uint32_t* b){
    asm volatile(
        "mma.sync.aligned.m16n8k8.row.col.f32.tf32.tf32.f32 "
        "{%0,%1,%2,%3}, {%4,%5,%6,%7}, {%8,%9}, {%0,%1,%2,%3};"
        : "+f"(c[0]), "+f"(c[1]), "+f"(c[2]), "+f"(c[3])
        : "r"(a[0]), "r"(a[1]), "r"(a[2]), "r"(a[3]), "r"(b[0]), "r"(b[1]));
}

__device__ __forceinline__ void cp16(void* smemDst, const void* gSrc){
    uint32_t s = (uint32_t)__cvta_generic_to_shared(smemDst);
    asm volatile("cp.async.ca.shared.global [%0], [%1], 16;" :: "r"(s), "l"(gSrc) : "memory");
}
__device__ __forceinline__ void cp_commit(){ asm volatile("cp.async.commit_group;" ::: "memory"); }
template<int NN> __device__ __forceinline__ void cp_wait(){ asm volatile("cp.async.wait_group %0;" :: "n"(NN) : "memory"); }

// ---------------- prep: pack xyz2 (+norm), precompute BN scale/shift ----------------
__global__ void prep_kernel(const float* __restrict__ xyz2,
                            const float* __restrict__ G0, const float* __restrict__ B0,
                            const float* __restrict__ M0, const float* __restrict__ V0,
                            const float* __restrict__ G1, const float* __restrict__ B1,
                            const float* __restrict__ M1, const float* __restrict__ V1)
{
    int i = blockIdx.x*256 + threadIdx.x;
    if (i < BB*MP){
        float x = xyz2[i*3+0], y = xyz2[i*3+1], z = xyz2[i*3+2];
        g_xyz2p[i] = make_float4(x, y, z, x*x + y*y + z*z);
    }
    if (blockIdx.x == 0){
        int t = threadIdx.x;
        if (t < D0){ float s = G0[t]*rsqrtf(V0[t]+1e-3f); g_sc0[t]=s; g_sh0[t]=B0[t]-M0[t]*s; }
        if (t < D1){ float s = G1[t]*rsqrtf(V1[t]+1e-3f); g_sc1[t]=s; g_sh1[t]=B1[t]-M1[t]*s; }
    }
}

// ---------------- 3-NN brute force (one query per thread) ----------------
__global__ void __launch_bounds__(128) nn3_kernel(const float* __restrict__ xyz1)
{
    __shared__ float4 s[2048];
    const int q = blockIdx.x*128 + threadIdx.x;
    const int b = q >> 14;                 // q / NQ
    const float x = xyz1[q*3+0], y = xyz1[q*3+1], z = xyz1[q*3+2];
    const float n1 = x*x + y*y + z*z;
    const float ax = -2.f*x, ay = -2.f*y, az = -2.f*z;

    float b0v = 3.0e37f, b1v = 3.0e37f, b2v = 3.0e37f;   // in (d2 - n1) space
    int   i0 = 0, i1 = 0, i2 = 0;

    for (int half = 0; half < 2; ++half){
        const float4* src = g_xyz2p + b*MP + half*2048;
        __syncthreads();
        for (int m = threadIdx.x; m < 2048; m += 128) s[m] = src[m];
        __syncthreads();
        #pragma unroll 4
        for (int m = 0; m < 2048; ++m){
            float4 t = s[m];
            float d = fmaf(az, t.z, fmaf(ay, t.y, fmaf(ax, t.x, t.w)));
            if (d < b2v){
                int gm = (half << 11) + m;
                if (d < b1v){
                    b2v = b1v; i2 = i1;
                    if (d < b0v){ b1v = b0v; i1 = i0; b0v = d; i0 = gm; }
                    else        { b1v = d;   i1 = gm; }
                } else { b2v = d; i2 = gm; }
            }
        }
    }

    float d0 = fmaxf(n1 + b0v, 1e-10f);
    float d1 = fmaxf(n1 + b1v, 1e-10f);
    float d2 = fmaxf(n1 + b2v, 1e-10f);
    float w0 = 1.f/d0, w1 = 1.f/d1, w2 = 1.f/d2;
    float inv = 1.f/(w0 + w1 + w2);
    g_wgt[q*3+0] = w0*inv; g_wgt[q*3+1] = w1*inv; g_wgt[q*3+2] = w2*inv;
    g_idx[q*3+0] = i0;     g_idx[q*3+1] = i1;     g_idx[q*3+2] = i2;
}

// ---------------- weighted gather of P2W rows -> first-layer partial sum ----------------
__global__ void __launch_bounds__(256) gather_kernel()
{
    int t = blockIdx.x*256 + threadIdx.x;
    int q = t >> 6;          // 64 threads per query (256 floats as float4)
    int c = t & 63;
    int b = q >> 14;
    float w0 = g_wgt[q*3+0], w1 = g_wgt[q*3+1], w2 = g_wgt[q*3+2];
    const float4* P = (const float4*)g_P2W;
    int base = b * (MP * (D0/4));
    float4 p0 = P[base + g_idx[q*3+0]*(D0/4) + c];
    float4 p1 = P[base + g_idx[q*3+1]*(D0/4) + c];
    float4 p2 = P[base + g_idx[q*3+2]*(D0/4) + c];
    float4 r;
    r.x = w0*p0.x + w1*p1.x + w2*p2.x;
    r.y = w0*p0.y + w1*p1.y + w2*p2.y;
    r.z = w0*p0.z + w1*p1.z + w2*p2.z;
    r.w = w0*p0.w + w1*p1.w + w2*p2.w;
    ((float4*)g_G1)[(size_t)q*(D0/4) + c] = r;
}

// ---------------- tf32 tensor-core GEMM: out = epi(A[M,K] @ W[K,Nc] (+G) ) ----------------
// BM=128, BN=64, BK=16, 256 threads (8 warps: 4 along M x 2 along N), double-buffered cp.async
template<bool ADD_G, bool DO_BN>
__global__ void __launch_bounds__(256) gemm_tf32_kernel(
    const float* __restrict__ A, const float* __restrict__ W,
    const float* __restrict__ G, const float* __restrict__ scale,
    const float* __restrict__ shift, float* __restrict__ out,
    int K, int Nc)
{
    __shared__ float As[2][128*20];   // stride 20 floats: 16B-aligned, conflict-free frag reads
    __shared__ float Bs[2][16*72];    // stride 72 floats: 16B-aligned, conflict-free frag reads

    const int tid  = threadIdx.x;
    const int lane = tid & 31, warp = tid >> 5;
    const int wm = warp & 3, wn = warp >> 2;
    const int mBase = blockIdx.x * 128;
    const int nBase = blockIdx.y * 64;

    float acc[2][4][4];
    #pragma unroll
    for (int a = 0; a < 2; ++a)
        #pragma unroll
        for (int bq = 0; bq < 4; ++bq)
            #pragma unroll
            for (int c = 0; c < 4; ++c) acc[a][bq][c] = 0.f;

    const int ar = tid >> 2;            // 0..63
    const int ac = (tid & 3) * 4;       // 0,4,8,12
    const int br = tid >> 4;            // 0..15
    const int bc = (tid & 15) * 4;

    const float* Abase = A + (size_t)(mBase + ar) * K + ac;
    const float* Wbase = W + (size_t)br * Nc + nBase + bc;

    auto load_tile = [&](int kt, int buf){
        const float* a0 = Abase + kt*16;
        cp16(&As[buf][ar*20 + ac],        a0);
        cp16(&As[buf][(ar+64)*20 + ac],   a0 + (size_t)64*K);
        cp16(&Bs[buf][br*72 + bc],        Wbase + (size_t)kt*16*Nc);
        cp_commit();
    };

    const int KT = K >> 4;
    load_tile(0, 0);
    for (int kt = 0; kt < KT; ++kt){
        const int buf = kt & 1;
        if (kt + 1 < KT){ load_tile(kt+1, buf^1); cp_wait<1>(); }
        else            { cp_wait<0>(); }
        __syncthreads();

        const float* Ab = &As[buf][0];
        const float* Bb = &Bs[buf][0];
        #pragma unroll
        for (int ks = 0; ks < 2; ++ks){
            const int k0 = ks*8;
            uint32_t afr[2][4];
            uint32_t bfr[4][2];
            const int arow = wm*32 + (lane >> 2);
            const int acol = k0 + (lane & 3);
            #pragma unroll
            for (int mt = 0; mt < 2; ++mt){
                const float* p = Ab + (arow + mt*16)*20 + acol;
                afr[mt][0] = f2tf(p[0]);
                afr[mt][1] = f2tf(p[8*20]);
                afr[mt][2] = f2tf(p[4]);
                afr[mt][3] = f2tf(p[8*20 + 4]);
            }
            const int bcol = wn*32 + (lane >> 2);
            const int bk   = k0 + (lane & 3);
            #pragma unroll
            for (int nt = 0; nt < 4; ++nt){
                const float* p = Bb + bk*72 + bcol + nt*8;
                bfr[nt][0] = f2tf(p[0]);
                bfr[nt][1] = f2tf(p[4*72]);
            }
            #pragma unroll
            for (int mt = 0; mt < 2; ++mt)
                #pragma unroll
                for (int nt = 0; nt < 4; ++nt)
                    mma_tf32(acc[mt][nt], afr[mt], bfr[nt]);
        }
        __syncthreads();
    }

    // epilogue
    #pragma unroll
    for (int mt = 0; mt < 2; ++mt){
        #pragma unroll
        for (int nt = 0; nt < 4; ++nt){
            const int c0 = nBase + wn*32 + nt*8 + (lane & 3)*2;
            #pragma unroll
            for (int h = 0; h < 2; ++h){
                const int r = mBase + wm*32 + mt*16 + (lane >> 2) + h*8;
                float v0 = acc[mt][nt][h*2+0];
                float v1 = acc[mt][nt][h*2+1];
                if (ADD_G){
                    v0 += G[(size_t)r*Nc + c0];
                    v1 += G[(size_t)r*Nc + c0 + 1];
                }
                if (DO_BN){
                    v0 = fmaxf(fmaf(v0, scale[c0],   shift[c0]),   0.f);
                    v1 = fmaxf(fmaf(v1, scale[c0+1], shift[c0+1]), 0.f);
                }
                out[(size_t)r*Nc + c0]     = v0;
                out[(size_t)r*Nc + c0 + 1] = v1;
            }
        }
    }
}

// ---------------- launch ----------------
extern "C" void kernel_launch(void* const* d_in, const int* in_sizes, int n_in,
                              void* d_out, int out_size)
{
    const float* xyz1    = (const float*)d_in[0];
    const float* xyz2    = (const float*)d_in[1];
    const float* points1 = (const float*)d_in[2];
    const float* points2 = (const float*)d_in[3];
    const float* w0 = (const float*)d_in[4];
    const float* g0 = (const float*)d_in[5];
    const float* b0 = (const float*)d_in[6];
    const float* m0 = (const float*)d_in[7];
    const float* v0 = (const float*)d_in[8];
    const float* w1 = (const float*)d_in[9];
    const float* g1 = (const float*)d_in[10];
    const float* b1 = (const float*)d_in[11];
    const float* m1 = (const float*)d_in[12];
    const float* v1 = (const float*)d_in[13];
    float* out = (float*)d_out;

    void *pP2W=nullptr, *pG1=nullptr, *pH=nullptr, *pSc0=nullptr, *pSh0=nullptr, *pSc1=nullptr, *pSh1=nullptr;
    cudaGetSymbolAddress(&pP2W, g_P2W);
    cudaGetSymbolAddress(&pG1,  g_G1);
    cudaGetSymbolAddress(&pH,   g_H);
    cudaGetSymbolAddress(&pSc0, g_sc0);
    cudaGetSymbolAddress(&pSh0, g_sh0);
    cudaGetSymbolAddress(&pSc1, g_sc1);
    cudaGetSymbolAddress(&pSh1, g_sh1);

    // 1) pack xyz2 + BN constants
    prep_kernel<<<64, 256>>>(xyz2, g0, b0, m0, v0, g1, b1, m1, v1);

    // 2) 3-NN (weights + indices)
    nn3_kernel<<<512, 128>>>(xyz1);

    // 3) P2W = points2 @ w0[0:256,:]   (M=16384, K=256, Nc=256)
    gemm_tf32_kernel<false,false><<<dim3(128, 4), 256>>>(
        points2, w0, nullptr, nullptr, nullptr, (float*)pP2W, 256, 256);

    // 4) G1 = weighted gather of P2W rows (= interp @ w0[0:256,:])
    gather_kernel<<<16384, 256>>>();

    // 5) H = relu(bn0(points1 @ w0[256:384,:] + G1))   (M=65536, K=128, Nc=256)
    gemm_tf32_kernel<true,true><<<dim3(512, 4), 256>>>(
        points1, w0 + 256*256, (const float*)pG1,
        (const float*)pSc0, (const float*)pSh0, (float*)pH, 128, 256);

    // 6) out = relu(bn1(H @ w1))   (M=65536, K=256, Nc=128)
    gemm_tf32_kernel<false,true><<<dim3(512, 2), 256>>>(
        (const float*)pH, w1, nullptr,
        (const float*)pSc1, (const float*)pSh1, out, 256, 128);
}